// round 1
// baseline (speedup 1.0000x reference)
#include <cuda_runtime.h>
#include <math.h>

#define BSZ 8
#define PP  16384          // points per batch
#define NPT (BSZ*PP)       // 131072
#define TOKD 768
#define MT  128
#define KNN 16
#define IHD 256

// ---------------- scratch (device globals; no allocation allowed) ----------------
__device__ float g_h1[(size_t)NPT*256];
__device__ float g_h2[(size_t)NPT*512];
__device__ float g_h3[(size_t)NPT*768];
__device__ float g_pf[(size_t)NPT*768];
__device__ float g_zin[(size_t)NPT*772];
__device__ float g_z1[(size_t)NPT*256];
__device__ float g_imp[NPT];
__device__ int   g_sel[BSZ*MT];
__device__ float g_pooled[(size_t)BSZ*MT*768];
__device__ float g_t1[(size_t)BSZ*MT*768];

// ---------------- generic tiled SGEMM: C = act(A @ W + bias) ----------------
// A: N x Kin (row-major), W: Kin x Kout (row-major), C: N x Kout
#define GBM 128
#define GBN 128
#define GBK 8
#define GTM 8
#define GTN 8

__global__ __launch_bounds__(256) void sgemm_bias_act(
    const float* __restrict__ A, const float* __restrict__ W,
    const float* __restrict__ bias, float* __restrict__ C,
    int N, int Kin, int Kout, int doRelu)
{
    __shared__ float As[GBK][GBM];
    __shared__ float Ws[GBK][GBN];
    const int bRow = blockIdx.y * GBM;
    const int bCol = blockIdx.x * GBN;
    const int tid  = threadIdx.x;
    const int tr = (tid / 16) * GTM;
    const int tc = (tid % 16) * GTN;

    float acc[GTM][GTN];
#pragma unroll
    for (int i = 0; i < GTM; i++)
#pragma unroll
        for (int j = 0; j < GTN; j++) acc[i][j] = 0.f;

    for (int k0 = 0; k0 < Kin; k0 += GBK) {
        // load A tile (128 rows x 8 k)
#pragma unroll
        for (int l = 0; l < 4; l++) {
            int e  = tid + l * 256;
            int ar = e >> 3;          // /8
            int ak = e & 7;
            int gr = bRow + ar, gk = k0 + ak;
            As[ak][ar] = (gk < Kin && gr < N) ? A[(size_t)gr * Kin + gk] : 0.f;
        }
        // load W tile (8 k x 128 cols), coalesced along Kout
#pragma unroll
        for (int l = 0; l < 4; l++) {
            int e  = tid + l * 256;
            int wk = e >> 7;          // /128
            int wc = e & 127;
            int gk = k0 + wk, gc = bCol + wc;
            Ws[wk][wc] = (gk < Kin && gc < Kout) ? W[(size_t)gk * Kout + gc] : 0.f;
        }
        __syncthreads();
#pragma unroll
        for (int kk = 0; kk < GBK; kk++) {
            float ra[GTM], rb[GTN];
#pragma unroll
            for (int i = 0; i < GTM; i++) ra[i] = As[kk][tr + i];
#pragma unroll
            for (int j = 0; j < GTN; j++) rb[j] = Ws[kk][tc + j];
#pragma unroll
            for (int i = 0; i < GTM; i++)
#pragma unroll
                for (int j = 0; j < GTN; j++) acc[i][j] += ra[i] * rb[j];
        }
        __syncthreads();
    }

#pragma unroll
    for (int i = 0; i < GTM; i++) {
        int gr = bRow + tr + i;
        if (gr >= N) continue;
#pragma unroll
        for (int j = 0; j < GTN; j++) {
            int gc = bCol + tc + j;
            if (gc >= Kout) continue;
            float v = acc[i][j] + bias[gc];
            if (doRelu) v = fmaxf(v, 0.f);
            C[(size_t)gr * Kout + gc] = v;
        }
    }
}

// ---------------- concat [pf | coords4] -> zin (N x 772) ----------------
__global__ void concat_kernel(const float* __restrict__ pf,
                              const float* __restrict__ coords,
                              float* __restrict__ zin, size_t total)
{
    size_t i = (size_t)blockIdx.x * blockDim.x + threadIdx.x;
    if (i >= total) return;
    size_t n = i / 772;
    int    c = (int)(i - n * 772);
    zin[i] = (c < 768) ? pf[n * 768 + c]
                       : coords[n * 5 + 1 + (c - 768)];
}

// ---------------- fused LN + z@iw2 relu + @iw3 importance ----------------
#define IPTS 16
__global__ __launch_bounds__(256) void importance_kernel(
    const float* __restrict__ z1, const float* __restrict__ iw2,
    const float* __restrict__ ib2, const float* __restrict__ iw3,
    const float* __restrict__ ib3, const float* __restrict__ ln_g,
    const float* __restrict__ ln_b, float* __restrict__ imp)
{
    __shared__ float zn[IPTS][IHD];
    __shared__ float red[IPTS][8];
    const int base = blockIdx.x * IPTS;
    const int tid  = threadIdx.x;
    const int w    = tid >> 5;
    const int lane = tid & 31;

    // LayerNorm: warp w handles points 2w and 2w+1
#pragma unroll
    for (int pp = 0; pp < 2; pp++) {
        int p = w * 2 + pp;
        float vals[8];
        float s = 0.f, s2 = 0.f;
#pragma unroll
        for (int j = 0; j < 8; j++) {
            float v = z1[(size_t)(base + p) * IHD + lane + j * 32];
            vals[j] = v; s += v; s2 += v * v;
        }
#pragma unroll
        for (int off = 16; off > 0; off >>= 1) {
            s  += __shfl_xor_sync(0xFFFFFFFFu, s,  off);
            s2 += __shfl_xor_sync(0xFFFFFFFFu, s2, off);
        }
        float mu  = s * (1.f / IHD);
        float var = s2 * (1.f / IHD) - mu * mu;
        float inv = rsqrtf(var + 1e-5f);
#pragma unroll
        for (int j = 0; j < 8; j++) {
            int c = lane + j * 32;
            zn[p][c] = (vals[j] - mu) * inv * ln_g[c] + ln_b[c];
        }
    }
    __syncthreads();

    // z2[t] for all IPTS points; t = tid
    float acc[IPTS];
#pragma unroll
    for (int p = 0; p < IPTS; p++) acc[p] = ib2[tid];
    for (int k = 0; k < IHD; k++) {
        float wv = iw2[k * IHD + tid];
#pragma unroll
        for (int p = 0; p < IPTS; p++) acc[p] += zn[p][k] * wv;
    }
    float w3v = iw3[tid];
#pragma unroll
    for (int p = 0; p < IPTS; p++) {
        float v = fmaxf(acc[p], 0.f) * w3v;
#pragma unroll
        for (int off = 16; off > 0; off >>= 1)
            v += __shfl_xor_sync(0xFFFFFFFFu, v, off);
        if (lane == 0) red[p][w] = v;
    }
    __syncthreads();
    if (tid < IPTS) {
        float s = 0.f;
#pragma unroll
        for (int ww = 0; ww < 8; ww++) s += red[tid][ww];
        imp[base + tid] = s + ib3[0];
    }
}

// ---------------- per-batch top-128 + sort by t + emit cents/masks ----------------
__global__ __launch_bounds__(1024) void topk_kernel(
    const float* __restrict__ imp, const float* __restrict__ coords,
    const float* __restrict__ noise, const float* __restrict__ log_temp,
    int* __restrict__ sel_out, float* __restrict__ out_cents,
    float* __restrict__ out_masks)
{
    extern __shared__ float pert[];     // PP floats
    __shared__ float rv[1024];
    __shared__ int   ri[1024];
    __shared__ float selT[MT];
    __shared__ int   selI[MT];
    const int b   = blockIdx.x;
    const int tid = threadIdx.x;

    float temp = fmaxf(expf(log_temp[0]), 0.1f);
    float itemp = 1.f / temp;
    for (int i = tid; i < PP; i += 1024)
        pert[i] = (imp[b * PP + i] + noise[b * PP + i]) * itemp;
    __syncthreads();

    for (int s = 0; s < MT; s++) {
        float best = -INFINITY; int bi = 0x7FFFFFFF;
        for (int i = tid; i < PP; i += 1024) {
            float v = pert[i];
            if (v > best) { best = v; bi = i; }
        }
        rv[tid] = best; ri[tid] = bi;
        __syncthreads();
        for (int off = 512; off > 0; off >>= 1) {
            if (tid < off) {
                float ov = rv[tid + off]; int oi = ri[tid + off];
                if (ov > rv[tid] || (ov == rv[tid] && oi < ri[tid])) {
                    rv[tid] = ov; ri[tid] = oi;
                }
            }
            __syncthreads();
        }
        if (tid == 0) {
            int idx = ri[0];
            selI[s] = idx;
            selT[s] = coords[((size_t)b * PP + idx) * 5 + 4];
            pert[idx] = -INFINITY;
        }
        __syncthreads();
    }

    // bitonic sort 128 selected by t ascending
    for (int kk = 2; kk <= MT; kk <<= 1) {
        for (int j = kk >> 1; j > 0; j >>= 1) {
            if (tid < MT) {
                int ixj = tid ^ j;
                if (ixj > tid) {
                    bool up = ((tid & kk) == 0);
                    float a = selT[tid], c = selT[ixj];
                    if ((a > c) == up) {
                        selT[tid] = c; selT[ixj] = a;
                        int t0 = selI[tid]; selI[tid] = selI[ixj]; selI[ixj] = t0;
                    }
                }
            }
            __syncthreads();
        }
    }

    if (tid < MT) {
        int idx = selI[tid];
        sel_out[b * MT + tid] = idx;
#pragma unroll
        for (int c = 0; c < 4; c++)
            out_cents[((size_t)b * MT + tid) * 4 + c] =
                coords[((size_t)b * PP + idx) * 5 + 1 + c];
        out_masks[b * MT + tid] = 1.0f;
    }
}

// ---------------- per-centroid 16-NN + max-pool of pf ----------------
__global__ __launch_bounds__(256) void knn_pool_kernel(
    const int* __restrict__ sel, const float* __restrict__ coords,
    const float* __restrict__ pf, float* __restrict__ pooled)
{
    extern __shared__ float d2[];   // PP floats
    __shared__ float rv[256];
    __shared__ int   ri[256];
    __shared__ int   knn[KNN];
    const int g   = blockIdx.x;     // b*MT + r
    const int b   = g >> 7;
    const int tid = threadIdx.x;

    int ci = sel[g];
    const float* cp = &coords[((size_t)b * PP + ci) * 5 + 1];
    float cx = cp[0], cy = cp[1], cz = cp[2], ct = cp[3];

    for (int i = tid; i < PP; i += 256) {
        const float* p = &coords[((size_t)b * PP + i) * 5 + 1];
        float dx = p[0] - cx, dy = p[1] - cy, dz = p[2] - cz, dt = p[3] - ct;
        d2[i] = dx * dx + dy * dy + dz * dz + dt * dt;
    }
    __syncthreads();

    for (int s = 0; s < KNN; s++) {
        float best = INFINITY; int bi = 0x7FFFFFFF;
        for (int i = tid; i < PP; i += 256) {
            float v = d2[i];
            if (v < best) { best = v; bi = i; }
        }
        rv[tid] = best; ri[tid] = bi;
        __syncthreads();
        for (int off = 128; off > 0; off >>= 1) {
            if (tid < off) {
                float ov = rv[tid + off]; int oi = ri[tid + off];
                if (ov < rv[tid] || (ov == rv[tid] && oi < ri[tid])) {
                    rv[tid] = ov; ri[tid] = oi;
                }
            }
            __syncthreads();
        }
        if (tid == 0) { knn[s] = ri[0]; d2[ri[0]] = INFINITY; }
        __syncthreads();
    }

    for (int j = tid; j < TOKD; j += 256) {
        float m = -INFINITY;
#pragma unroll
        for (int s = 0; s < KNN; s++)
            m = fmaxf(m, pf[((size_t)b * PP + knn[s]) * TOKD + j]);
        pooled[(size_t)g * TOKD + j] = m;
    }
}

// ---------------- launch ----------------
extern "C" void kernel_launch(void* const* d_in, const int* in_sizes, int n_in,
                              void* d_out, int out_size)
{
    const float* coords   = (const float*)d_in[0];
    const float* feats    = (const float*)d_in[1];
    const float* log_temp = (const float*)d_in[2];
    const float* w1 = (const float*)d_in[3];  const float* b1 = (const float*)d_in[4];
    const float* w2 = (const float*)d_in[5];  const float* b2 = (const float*)d_in[6];
    const float* w3 = (const float*)d_in[7];  const float* b3 = (const float*)d_in[8];
    const float* w4 = (const float*)d_in[9];  const float* b4 = (const float*)d_in[10];
    const float* iw1 = (const float*)d_in[11]; const float* ib1 = (const float*)d_in[12];
    const float* ln_g = (const float*)d_in[13]; const float* ln_b = (const float*)d_in[14];
    const float* iw2 = (const float*)d_in[15]; const float* ib2 = (const float*)d_in[16];
    const float* iw3 = (const float*)d_in[17]; const float* ib3 = (const float*)d_in[18];
    const float* nw1 = (const float*)d_in[19]; const float* nb1 = (const float*)d_in[20];
    const float* nw2 = (const float*)d_in[21]; const float* nb2 = (const float*)d_in[22];
    const float* noise = (const float*)d_in[23];

    float* out        = (float*)d_out;
    float* out_tokens = out;
    float* out_cents  = out + (size_t)BSZ * MT * TOKD;
    float* out_masks  = out_cents + (size_t)BSZ * MT * 4;

    float *h1, *h2, *h3, *pf, *zin, *z1, *imp, *pooled, *t1;
    int* sel;
    cudaGetSymbolAddress((void**)&h1,  g_h1);
    cudaGetSymbolAddress((void**)&h2,  g_h2);
    cudaGetSymbolAddress((void**)&h3,  g_h3);
    cudaGetSymbolAddress((void**)&pf,  g_pf);
    cudaGetSymbolAddress((void**)&zin, g_zin);
    cudaGetSymbolAddress((void**)&z1,  g_z1);
    cudaGetSymbolAddress((void**)&imp, g_imp);
    cudaGetSymbolAddress((void**)&sel, g_sel);
    cudaGetSymbolAddress((void**)&pooled, g_pooled);
    cudaGetSymbolAddress((void**)&t1,  g_t1);

    cudaFuncSetAttribute(topk_kernel,
        cudaFuncAttributeMaxDynamicSharedMemorySize, PP * sizeof(float));
    cudaFuncSetAttribute(knn_pool_kernel,
        cudaFuncAttributeMaxDynamicSharedMemorySize, PP * sizeof(float));

    dim3 blk(256);
    // 1-4: point MLP
    sgemm_bias_act<<<dim3((256 + GBN - 1) / GBN, (NPT + GBM - 1) / GBM), blk>>>(
        feats, w1, b1, h1, NPT, 6, 256, 1);
    sgemm_bias_act<<<dim3((512 + GBN - 1) / GBN, (NPT + GBM - 1) / GBM), blk>>>(
        h1, w2, b2, h2, NPT, 256, 512, 1);
    sgemm_bias_act<<<dim3((768 + GBN - 1) / GBN, (NPT + GBM - 1) / GBM), blk>>>(
        h2, w3, b3, h3, NPT, 512, 768, 1);
    sgemm_bias_act<<<dim3((768 + GBN - 1) / GBN, (NPT + GBM - 1) / GBM), blk>>>(
        h3, w4, b4, pf, NPT, 768, 768, 0);
    // 5: concat
    {
        size_t total = (size_t)NPT * 772;
        concat_kernel<<<(unsigned)((total + 255) / 256), 256>>>(pf, coords, zin, total);
    }
    // 6: importance layer 1
    sgemm_bias_act<<<dim3((256 + GBN - 1) / GBN, (NPT + GBM - 1) / GBM), blk>>>(
        zin, iw1, ib1, z1, NPT, 772, 256, 1);
    // 7: fused LN + mlp + importance score
    importance_kernel<<<NPT / IPTS, 256>>>(z1, iw2, ib2, iw3, ib3, ln_g, ln_b, imp);
    // 8: per-batch top-128 + sort by t + cents/masks out
    topk_kernel<<<BSZ, 1024, PP * sizeof(float)>>>(
        imp, coords, noise, log_temp, sel, out_cents, out_masks);
    // 9: knn + max pool
    knn_pool_kernel<<<BSZ * MT, 256, PP * sizeof(float)>>>(sel, coords, pf, pooled);
    // 10-11: token MLP (rows already in output order)
    sgemm_bias_act<<<dim3((768 + GBN - 1) / GBN, (BSZ * MT + GBM - 1) / GBM), blk>>>(
        pooled, nw1, nb1, t1, BSZ * MT, 768, 768, 1);
    sgemm_bias_act<<<dim3((768 + GBN - 1) / GBN, (BSZ * MT + GBM - 1) / GBM), blk>>>(
        t1, nw2, nb2, out_tokens, BSZ * MT, 768, 768, 0);
}